// round 1
// baseline (speedup 1.0000x reference)
#include <cuda_runtime.h>
#include <cstdint>
#include <cstddef>

// Net_quantize: fused MFL recurrence + LSQ fake-quant + 2 quantized linear layers.
//
// Inputs (metadata order): x(M*128), mfl_alpha(1), mfl_beta(1), a1(1), a2(1), a3(1),
//                          W1(16*128), b1(16), wa1(1), W2(10*16), b2(10), wa2(1)
// Output: out(M*10) float32
//
// Design: one thread per row. x staged through SMEM in 256x32 chunks (coalesced
// float4 loads, pad-33 conflict-free per-row reads). fc1/fc2 done with DP4A on
// the exact int8 quantization levels (fake_quant == int8_level * scale), so the
// integer accumulation is exact and only one scale multiply per output remains.

#define THREADS 256
#define RPB     256          // rows per block
#define NCOLS   128
#define CHUNK   32
#define XPAD    33           // 33-float row stride in smem -> conflict-free

__global__ __launch_bounds__(THREADS)
void net_quant_kernel(const float* __restrict__ x,
                      const float* __restrict__ p_alpha,
                      const float* __restrict__ p_beta,
                      const float* __restrict__ p_a1,
                      const float* __restrict__ p_a2,
                      const float* __restrict__ p_a3,
                      const float* __restrict__ W1,
                      const float* __restrict__ b1,
                      const float* __restrict__ p_wa1,
                      const float* __restrict__ W2,
                      const float* __restrict__ b2,
                      const float* __restrict__ p_wa2,
                      float* __restrict__ out)
{
    __shared__ float xs[RPB * XPAD];      // 33792 B (reused for output staging)
    __shared__ int   w1p[32 * 16];        // [kc][j], kc = k/4, bytes = cols 4kc..4kc+3
    __shared__ int   w2p[10 * 4];         // [j][c]

    const int tid  = threadIdx.x;
    const int row0 = blockIdx.x * RPB;

    const float alpha = p_alpha[0];
    const float beta  = p_beta[0];
    const float a1  = p_a1[0];
    const float a2  = p_a2[0];
    const float a3  = p_a3[0];
    const float wa1 = p_wa1[0];
    const float wa2 = p_wa2[0];
    const float inv_a1  = 1.0f / a1;
    const float inv_a2  = 1.0f / a2;
    const float inv_a3  = 1.0f / a3;
    const float inv_wa1 = 1.0f / wa1;
    const float inv_wa2 = 1.0f / wa2;

    // ---- quantize + pack W1 (16x128) into smem, layout [kc][j] for int4 loads ----
    for (int i = tid; i < 512; i += THREADS) {
        const int kc = i >> 4, j = i & 15;
        unsigned v = 0;
#pragma unroll
        for (int b = 0; b < 4; ++b) {
            float t = W1[j * 128 + kc * 4 + b] * inv_wa1;
            t = fminf(fmaxf(t, -128.0f), 127.0f);
            const int q = __float2int_rn(t);
            v |= ((unsigned)(q & 0xff)) << (8 * b);
        }
        w1p[i] = (int)v;
    }
    // ---- quantize + pack W2 (10x16) ----
    if (tid < 40) {
        const int j = tid >> 2, c = tid & 3;
        unsigned v = 0;
#pragma unroll
        for (int b = 0; b < 4; ++b) {
            float t = W2[j * 16 + c * 4 + b] * inv_wa2;
            t = fminf(fmaxf(t, -128.0f), 127.0f);
            const int q = __float2int_rn(t);
            v |= ((unsigned)(q & 0xff)) << (8 * b);
        }
        w2p[tid] = (int)v;
    }
    // (first __syncthreads below, after chunk-0 staging, orders w1p/w2p for all)

    // ---- MFL recurrence + fc1 (int8 dp4a accumulation) ----
    float w = 1.0f;
    int acc[16];
#pragma unroll
    for (int j = 0; j < 16; ++j) acc[j] = 0;
    unsigned hp = 0;

    for (int chunk = 0; chunk < 4; ++chunk) {
        // coalesced stage: 256 rows x 32 cols
#pragma unroll
        for (int it = 0; it < 8; ++it) {
            const int i = it * THREADS + tid;      // 0..2047
            const int r = i >> 3, q = i & 7;
            const float4 v = *reinterpret_cast<const float4*>(
                x + (size_t)(row0 + r) * NCOLS + chunk * CHUNK + q * 4);
            float* d = &xs[r * XPAD + q * 4];
            d[0] = v.x; d[1] = v.y; d[2] = v.z; d[3] = v.w;
        }
        __syncthreads();

#pragma unroll
        for (int kk = 0; kk < CHUNK; ++kk) {
            // h_k = fake_quant(w_k, a1) as int8 level
            float t = w * inv_a1;
            t = fminf(fmaxf(t, -128.0f), 127.0f);
            const int hq = __float2int_rn(t);
            hp = (hp >> 8) | (((unsigned)hq & 0xffu) << 24);

            if ((kk & 3) == 3) {
                const int kc = chunk * 8 + (kk >> 2);
                const int4* wp = reinterpret_cast<const int4*>(&w1p[kc * 16]);
                const int4 w0 = wp[0], w1v = wp[1], w2v = wp[2], w3v = wp[3];
                acc[0]  = __dp4a((int)hp, w0.x,  acc[0]);
                acc[1]  = __dp4a((int)hp, w0.y,  acc[1]);
                acc[2]  = __dp4a((int)hp, w0.z,  acc[2]);
                acc[3]  = __dp4a((int)hp, w0.w,  acc[3]);
                acc[4]  = __dp4a((int)hp, w1v.x, acc[4]);
                acc[5]  = __dp4a((int)hp, w1v.y, acc[5]);
                acc[6]  = __dp4a((int)hp, w1v.z, acc[6]);
                acc[7]  = __dp4a((int)hp, w1v.w, acc[7]);
                acc[8]  = __dp4a((int)hp, w2v.x, acc[8]);
                acc[9]  = __dp4a((int)hp, w2v.y, acc[9]);
                acc[10] = __dp4a((int)hp, w2v.z, acc[10]);
                acc[11] = __dp4a((int)hp, w2v.w, acc[11]);
                acc[12] = __dp4a((int)hp, w3v.x, acc[12]);
                acc[13] = __dp4a((int)hp, w3v.y, acc[13]);
                acc[14] = __dp4a((int)hp, w3v.z, acc[14]);
                acc[15] = __dp4a((int)hp, w3v.w, acc[15]);
            }

            // advance recurrence: w += alpha/w - beta*x_k
            const float xv = xs[tid * XPAD + kk];
            float r;
            asm("rcp.approx.f32 %0, %1;" : "=f"(r) : "f"(w));
            r = __fmaf_rn(r, __fmaf_rn(-w, r, 1.0f), r);        // one Newton -> ~1ulp
            w = __fmaf_rn(-beta, xv, __fmaf_rn(alpha, r, w));
        }
        __syncthreads();
    }

    // ---- epilogue: bias, sigmoid, unsigned quant, signed quant, fc2 (dp4a) ----
    const float s1scale = a1 * wa1;
    unsigned sp[4];
    unsigned spacc = 0;
#pragma unroll
    for (int j = 0; j < 16; ++j) {
        const float h = __fmaf_rn((float)acc[j], s1scale, b1[j]);
        const float sg = __fdividef(1.0f, 1.0f + __expf(-h));
        float u = sg * inv_a2;
        u = fminf(fmaxf(u, 0.0f), 255.0f);
        const float s = (float)__float2int_rn(u) * a2;          // post-sigmoid fq
        float v2 = s * inv_a3;
        v2 = fminf(fmaxf(v2, -128.0f), 127.0f);
        const int s2q = __float2int_rn(v2);                     // qAct3 level
        spacc = (spacc >> 8) | (((unsigned)s2q & 0xffu) << 24);
        if ((j & 3) == 3) sp[j >> 2] = spacc;
    }

    const float s2scale = a3 * wa2;
    float* outs = xs;   // reuse staging buffer (all xs readers passed the last sync)
#pragma unroll
    for (int j = 0; j < 10; ++j) {
        int o = 0;
        o = __dp4a((int)sp[0], w2p[j * 4 + 0], o);
        o = __dp4a((int)sp[1], w2p[j * 4 + 1], o);
        o = __dp4a((int)sp[2], w2p[j * 4 + 2], o);
        o = __dp4a((int)sp[3], w2p[j * 4 + 3], o);
        outs[tid * 10 + j] = __fmaf_rn((float)o, s2scale, b2[j]);
    }
    __syncthreads();

    // coalesced output store: 2560 contiguous floats per block
#pragma unroll
    for (int t = 0; t < 10; ++t) {
        const int i = t * THREADS + tid;
        out[(size_t)row0 * 10 + i] = outs[i];
    }
}

extern "C" void kernel_launch(void* const* d_in, const int* in_sizes, int n_in,
                              void* d_out, int out_size)
{
    const float* x       = (const float*)d_in[0];
    const float* p_alpha = (const float*)d_in[1];
    const float* p_beta  = (const float*)d_in[2];
    const float* p_a1    = (const float*)d_in[3];
    const float* p_a2    = (const float*)d_in[4];
    const float* p_a3    = (const float*)d_in[5];
    const float* W1      = (const float*)d_in[6];
    const float* b1      = (const float*)d_in[7];
    const float* p_wa1   = (const float*)d_in[8];
    const float* W2      = (const float*)d_in[9];
    const float* b2      = (const float*)d_in[10];
    const float* p_wa2   = (const float*)d_in[11];
    float* out = (float*)d_out;

    const int M = in_sizes[0] / NCOLS;     // 262144
    const int blocks = M / RPB;            // 1024 (M divisible by 256 for this problem)

    net_quant_kernel<<<blocks, THREADS>>>(x, p_alpha, p_beta, p_a1, p_a2, p_a3,
                                          W1, b1, p_wa1, W2, b2, p_wa2, out);
}